// round 12
// baseline (speedup 1.0000x reference)
#include <cuda_runtime.h>
#include <cstdint>

// Problem constants (fixed by setup_inputs)
#define BATCH 8
#define H 1024
#define W 1024
#define HW (H*W)
#define TH 512
#define TW 512
#define NCELL (TH*TW)                    // 262144 = 2^18
#define COORDS_ELEMS (BATCH*NCELL*4*2)   // 16777216
#define WEIGHTS_ELEMS (BATCH*NCELL*4)    // 8388608
#define CTILES 1024                      // 32x32 contrast tiles per image
#define NCONTRAST (BATCH*CTILES)         // 8192

// Scratch (static device globals — allocation-free per harness rules)
__device__ float g_contrast[BATCH*HW];
__device__ float g_bmn[NCONTRAST];
__device__ float g_bmx[NCONTRAST];

// ---------------------------------------------------------------------------
// JAX threefry2x32, key = jax.random.key(42) -> (0, 42)
// ---------------------------------------------------------------------------
__device__ __forceinline__ unsigned rotl32(unsigned x, int r) {
    return __funnelshift_l(x, x, r);
}

__device__ __forceinline__ void threefry2x32(unsigned x0, unsigned x1,
                                             unsigned& o0, unsigned& o1) {
    const unsigned ks0 = 0u, ks1 = 42u, ks2 = 0x1BD11BF0u;
    x0 += ks0; x1 += ks1;
#define TFR(r) { x0 += x1; x1 = rotl32(x1, r); x1 ^= x0; }
    TFR(13) TFR(15) TFR(26) TFR(6)
    x0 += ks1; x1 += ks2 + 1u;
    TFR(17) TFR(29) TFR(16) TFR(24)
    x0 += ks2; x1 += ks0 + 2u;
    TFR(13) TFR(15) TFR(26) TFR(6)
    x0 += ks0; x1 += ks1 + 3u;
    TFR(17) TFR(29) TFR(16) TFR(24)
    x0 += ks1; x1 += ks2 + 4u;
    TFR(13) TFR(15) TFR(26) TFR(6)
    x0 += ks2; x1 += ks0 + 5u;
#undef TFR
    o0 = x0; o1 = x1;
}

__device__ __forceinline__ float tf_uniform(unsigned flat_idx) {
    unsigned o0, o1;
    threefry2x32(0u, flat_idx, o0, o1);
    unsigned bits = o0 ^ o1;
    return __uint_as_float((bits >> 9) | 0x3f800000u) - 1.0f;
}

// named barrier for the contrast half (8 warps = 256 threads) only
#define CONTRAST_BAR() asm volatile("bar.sync 1, 256;" ::: "memory")

// ---------------------------------------------------------------------------
// K1: WARP-SPECIALIZED fat kernel. One 512-thread block per contrast tile:
//   warps 0-7  : gray+contrast 32x32 smem tile (sync via named barrier 1)
//   warps 8-15 : 256 threefry cells (no barriers)
// Guarantees every SM holds both the alu-saturated threefry stream and the
// fma/LSU contrast stream -> per-warp interleaving, no scheduler luck.
// ---------------------------------------------------------------------------
__global__ void __launch_bounds__(512, 2)
k_main1(const float* __restrict__ img,
        float* __restrict__ coords) {
    __shared__ float sg[36][37];
    __shared__ float wmn[8], wmx[8];

    const int cid = blockIdx.x;                    // 0..8191 (tile id)
    const int tid = threadIdx.x;

    if (tid < 256) {
        // ---------------- contrast tile (32x32, smem gray halo) ------------
        const int lin = tid;
        const int b    = cid >> 10;
        const int tile = cid & (CTILES - 1);
        const int by0 = (tile >> 5) * 32;
        const int bx0 = (tile & 31) * 32;

        const float* ib = img + (size_t)b * 3 * HW;

        // gray fill: interior fast path (no predicates) vs border path
        if (bx0 != 0 && bx0 != W - 32 && by0 != 0 && by0 != H - 32) {
            for (int e = lin; e < 36 * 36; e += 256) {
                int r = e / 36, c = e - r * 36;
                int p = (by0 + r - 2) * W + (bx0 + c - 2);
                sg[r][c] = __ldg(ib + p) * 0.299f + __ldg(ib + HW + p) * 0.587f
                         + __ldg(ib + 2 * HW + p) * 0.114f;
            }
        } else {
            for (int e = lin; e < 36 * 36; e += 256) {
                int r = e / 36, c = e - r * 36;
                int gy = by0 + r - 2, gx = bx0 + c - 2;
                float v = 0.0f;
                if ((unsigned)gy < H && (unsigned)gx < W) {
                    int p = gy * W + gx;
                    v = __ldg(ib + p) * 0.299f + __ldg(ib + HW + p) * 0.587f
                      + __ldg(ib + 2 * HW + p) * 0.114f;
                }
                sg[r][c] = v;
            }
        }
        CONTRAST_BAR();

        // compute: 8 strips (4 cols) x 32 rows; one strip-row per thread
        const int strip = lin & 7;                 // 0..7
        const int ry    = lin >> 3;                // 0..31
        const int y     = by0 + ry;
        const int ly    = ry + 2;
        const int c0    = strip * 4;
        const int lc    = c0 + 2;

        float r0[6], rc[6], r1[6];
#pragma unroll
        for (int i = 0; i < 6; ++i) {
            r0[i] = sg[ly - 1][lc - 1 + i];
            rc[i] = sg[ly    ][lc - 1 + i];
            r1[i] = sg[ly + 1][lc - 1 + i];
        }

        float cmin = 3.402823466e+38f, cmax = 0.0f;
        float cc[4];
#pragma unroll
        for (int i = 0; i < 4; ++i) {
            float a00 = r0[i], a01 = r0[i+1], a02 = r0[i+2];
            float a10 = rc[i], a11 = rc[i+1], a12 = rc[i+2];
            float a20 = r1[i], a21 = r1[i+1], a22 = r1[i+2];

            float gx2 = (a02 - a00) + 2.0f * (a12 - a10) + (a22 - a20);
            float gy2 = (a20 - a00) + 2.0f * (a21 - a01) + (a22 - a02);
            float sobel = sqrtf(gx2 * gx2 + gy2 * gy2 + 1e-8f);
            float lapl  = fabsf(4.0f * a11 - a01 - a10 - a12 - a21);

            const int x = bx0 + c0 + i;
            float dx = a12 - a10;
            if (x == 0)     dx = rc[3] - rc[1];
            if (x == W - 1) dx = rc[4] - rc[2];
            float dy = a21 - a01;
            if (y == 0)     dy = sg[ly + 2][lc + i] - sg[ly][lc + i];
            if (y == H - 1) dy = sg[ly][lc + i] - sg[ly - 2][lc + i];
            float gradm = sqrtf(dx * dx + dy * dy + 1e-8f);

            cc[i] = 0.5f * sobel + 0.3f * lapl + 0.2f * gradm;
            cmin = fminf(cmin, cc[i]);
            cmax = fmaxf(cmax, cc[i]);
        }
        float4 cv; cv.x = cc[0]; cv.y = cc[1]; cv.z = cc[2]; cv.w = cc[3];
        *(float4*)(g_contrast + b * HW + y * W + bx0 + c0) = cv;

#pragma unroll
        for (int s = 16; s > 0; s >>= 1) {
            cmin = fminf(cmin, __shfl_xor_sync(0xFFFFFFFFu, cmin, s));
            cmax = fmaxf(cmax, __shfl_xor_sync(0xFFFFFFFFu, cmax, s));
        }
        const int wid = lin >> 5;
        if ((lin & 31) == 0) { wmn[wid] = cmin; wmx[wid] = cmax; }
        CONTRAST_BAR();
        if (lin == 0) {
            float mn = wmn[0], mx = wmx[0];
#pragma unroll
            for (int s = 1; s < 8; ++s) {
                mn = fminf(mn, wmn[s]);
                mx = fmaxf(mx, wmx[s]);
            }
            g_bmn[cid] = mn;
            g_bmx[cid] = mx;
        }
    } else {
        // ---------------- threefry coords (img-independent, 1 cell/thread) -
        const int t = cid * 256 + (tid - 256);     // 0 .. 2M-1
        const int cell = t & (NCELL - 1);
        const int i = cell >> 9;
        const int j = cell & (TW - 1);

        float by = -1.0f + (float)i * (2.0f / 511.0f);
        float bx = -1.0f + (float)j * (2.0f / 511.0f);
        const float CELLSZ = 0.00390625f;   // 2/512 exact

        unsigned ctr = (unsigned)t * 8u;
        float u[8];
#pragma unroll
        for (int s = 0; s < 8; ++s) u[s] = tf_uniform(ctr + s);

        float4 c0, c1;
        c0.x = by + ((u[0] - 0.5f) * 0.8f) * CELLSZ;
        c0.y = bx + ((u[1] - 0.5f) * 0.8f) * CELLSZ;
        c0.z = by + ((u[2] - 0.5f) * 0.8f) * CELLSZ;
        c0.w = bx + ((u[3] - 0.5f) * 0.8f) * CELLSZ;
        c1.x = by + ((u[4] - 0.5f) * 0.8f) * CELLSZ;
        c1.y = bx + ((u[5] - 0.5f) * 0.8f) * CELLSZ;
        c1.z = by + ((u[6] - 0.5f) * 0.8f) * CELLSZ;
        c1.w = bx + ((u[7] - 0.5f) * 0.8f) * CELLSZ;

        float4* cp = (float4*)coords;
        cp[(size_t)t * 2]     = c0;
        cp[(size_t)t * 2 + 1] = c1;
    }
}

// ---------------------------------------------------------------------------
// horizontal 5-tap of zero-padded contrast at row y, cols x4..x4+3.
// ---------------------------------------------------------------------------
__device__ __forceinline__ float4 hconv(const float* __restrict__ cb,
                                        int y, int x4,
                                        float w0, float w1, float w2,
                                        float w3, float w4) {
    float4 r;
    if ((unsigned)y >= H) { r.x = r.y = r.z = r.w = 0.0f; return r; }
    const float* rp = cb + y * W + x4;
    float f0,f1,f2,f3,f4,f5,f6,f7;
    if (x4 >= 4) {
        float4 a = *(const float4*)(rp - 4);
        f0 = a.z; f1 = a.w;
    } else { f0 = f1 = 0.0f; }
    {
        float4 a = *(const float4*)rp;
        f2 = a.x; f3 = a.y; f4 = a.z; f5 = a.w;
    }
    if (x4 + 4 < W) {
        float4 a = *(const float4*)(rp + 4);
        f6 = a.x; f7 = a.y;
    } else { f6 = f7 = 0.0f; }
    r.x = w0*f0 + w1*f1 + w2*f2 + w3*f3 + w4*f4;
    r.y = w0*f1 + w1*f2 + w2*f3 + w3*f4 + w4*f5;
    r.z = w0*f2 + w1*f3 + w2*f4 + w3*f5 + w4*f6;
    r.w = w0*f3 + w1*f4 + w2*f5 + w3*f6 + w4*f7;
    return r;
}

// per-cell weights + ns==1 coords fixup (K1 wrote base+offset coords;
// launch boundary orders the writes).
__device__ __forceinline__ void do_cell(float d, int b, int i, int j,
                                        float* __restrict__ coords,
                                        float* __restrict__ weights) {
    int ns = (d > 0.7f) ? 4 : ((d > 0.4f) ? 2 : 1);
    float wv = d / (float)ns;
    int t = b * NCELL + i * TW + j;
    float4 w4;
    w4.x = wv;
    w4.y = (ns > 1) ? wv : 0.0f;
    w4.z = (ns > 3) ? wv : 0.0f;
    w4.w = (ns > 3) ? wv : 0.0f;
    ((float4*)weights)[t] = w4;
    if (ns == 1) {
        float by = -1.0f + (float)i * (2.0f / 511.0f);
        float bx = -1.0f + (float)j * (2.0f / 511.0f);
        float4 c0; c0.x = by; c0.y = bx; c0.z = by; c0.w = bx;
        float4* cp = (float4*)coords;
        cp[(size_t)t * 2]     = c0;
        cp[(size_t)t * 2 + 1] = c0;
    }
}

// ---------------------------------------------------------------------------
// K2: register-rolling separable gaussian + density + weights + fixup.
// Block (32,8) -> 128x64 tile (1024 blocks); thread owns 4 cols x 8 rows.
// ---------------------------------------------------------------------------
__global__ void __launch_bounds__(256, 4)
k_main2(float* __restrict__ dens_out,
        float* __restrict__ coords,
        float* __restrict__ weights) {
    __shared__ float rmn[8], rmx[8];

    const int b   = blockIdx.z;
    const int bx0 = blockIdx.x * 128;
    const int by0 = blockIdx.y * 64;
    const int tx = threadIdx.x, ty = threadIdx.y;
    const int lin = ty * 32 + tx;

    // --- batch min/max from per-block results (exact: min/max associative)
    {
        float mn_ = 3.402823466e+38f, mx_ = 0.0f;
        for (int e = lin; e < CTILES; e += 256) {
            mn_ = fminf(mn_, g_bmn[b * CTILES + e]);
            mx_ = fmaxf(mx_, g_bmx[b * CTILES + e]);
        }
#pragma unroll
        for (int s = 16; s > 0; s >>= 1) {
            mn_ = fminf(mn_, __shfl_xor_sync(0xFFFFFFFFu, mn_, s));
            mx_ = fmaxf(mx_, __shfl_xor_sync(0xFFFFFFFFu, mx_, s));
        }
        if (tx == 0) { rmn[ty] = mn_; rmx[ty] = mx_; }
    }
    __syncthreads();
    float mn = rmn[0], mx = rmx[0];
#pragma unroll
    for (int s = 1; s < 8; ++s) {
        mn = fminf(mn, rmn[s]);
        mx = fmaxf(mx, rmx[s]);
    }
    const bool ok = mx > mn;
    const float inv = ok ? 1.0f / (mx - mn) : 0.0f;

    // gaussian weights (same fp path as reference)
    const float sg2 = (5.0f / 6.0f) * (5.0f / 6.0f);
    const float e1 = expf(-0.5f / sg2);
    const float e2 = expf(-2.0f / sg2);
    const float ksum = 1.0f + 2.0f * e1 + 2.0f * e2;
    float w[5];
    w[0] = e2 / ksum; w[1] = e1 / ksum; w[2] = 1.0f / ksum; w[3] = w[1]; w[4] = w[0];
    const float w0 = w[0], w1 = w[1], w2 = w[2], w3 = w[3], w4 = w[4];
    const float wsum = ((((w[0] + w[1]) + w[2]) + w[3]) + w[4]);

    const int x4 = bx0 + tx * 4;

    float wxv0 = 0.f, wxv1 = 0.f, wxv2 = 0.f, wxv3 = 0.f;
#pragma unroll
    for (int d = 0; d < 5; ++d) {
        if ((unsigned)(x4 + 0 + d - 2) < W) wxv0 += w[d];
        if ((unsigned)(x4 + 1 + d - 2) < W) wxv1 += w[d];
        if ((unsigned)(x4 + 2 + d - 2) < W) wxv2 += w[d];
        if ((unsigned)(x4 + 3 + d - 2) < W) wxv3 += w[d];
    }

    const float* cb = g_contrast + b * HW;
    const int ys = by0 + ty * 8;

    float4 h0 = hconv(cb, ys - 2, x4, w0, w1, w2, w3, w4);
    float4 h1 = hconv(cb, ys - 1, x4, w0, w1, w2, w3, w4);
    float4 h2 = hconv(cb, ys,     x4, w0, w1, w2, w3, w4);
    float4 h3 = hconv(cb, ys + 1, x4, w0, w1, w2, w3, w4);

    float* drow = dens_out + b * HW + ys * W + x4;

#pragma unroll
    for (int s = 0; s < 8; ++s) {
        const int y = ys + s;
        float4 h4 = hconv(cb, y + 2, x4, w0, w1, w2, w3, w4);

        float4 acc;
        acc.x = w0*h0.x + w1*h1.x + w2*h2.x + w3*h3.x + w4*h4.x;
        acc.y = w0*h0.y + w1*h1.y + w2*h2.y + w3*h3.y + w4*h4.y;
        acc.z = w0*h0.z + w1*h1.z + w2*h2.z + w3*h3.z + w4*h4.z;
        acc.w = w0*h0.w + w1*h1.w + w2*h2.w + w3*h3.w + w4*h4.w;

        float wyv = wsum;
        if (y < 2 || y >= H - 2) {
            wyv = 0.0f;
#pragma unroll
            for (int d = 0; d < 5; ++d)
                if ((unsigned)(y + d - 2) < H) wyv += w[d];
        }

        float4 dv;
        dv.x = 0.1f + 0.9f * sqrtf(fmaxf(inv * (acc.x - mn * (wyv * wxv0)), 0.0f));
        dv.y = 0.1f + 0.9f * sqrtf(fmaxf(inv * (acc.y - mn * (wyv * wxv1)), 0.0f));
        dv.z = 0.1f + 0.9f * sqrtf(fmaxf(inv * (acc.z - mn * (wyv * wxv2)), 0.0f));
        dv.w = 0.1f + 0.9f * sqrtf(fmaxf(inv * (acc.w - mn * (wyv * wxv3)), 0.0f));

        *(float4*)drow = dv;
        drow += W;

        if ((y & 1) == 0) {
            const int i = y >> 1;
            const int j0 = x4 >> 1;
            do_cell(dv.x, b, i, j0,     coords, weights);
            do_cell(dv.z, b, i, j0 + 1, coords, weights);
        }

        h0 = h1; h1 = h2; h2 = h3; h3 = h4;
    }
}

// ---------------------------------------------------------------------------
extern "C" void kernel_launch(void* const* d_in, const int* in_sizes, int n_in,
                              void* d_out, int out_size) {
    const float* img = (const float*)d_in[0];
    float* out = (float*)d_out;
    float* coords  = out;
    float* weights = out + COORDS_ELEMS;
    float* dens    = out + COORDS_ELEMS + WEIGHTS_ELEMS;

    k_main1<<<NCONTRAST, 512>>>(img, coords);
    {
        dim3 grid(W / 128, H / 64, BATCH), block(32, 8);
        k_main2<<<grid, block>>>(dens, coords, weights);
    }
}

// round 14
// speedup vs baseline: 1.0638x; 1.0638x over previous
#include <cuda_runtime.h>
#include <cstdint>

// Problem constants (fixed by setup_inputs)
#define BATCH 8
#define H 1024
#define W 1024
#define HW (H*W)
#define TH 512
#define TW 512
#define NCELL (TH*TW)                    // 262144 = 2^18
#define COORDS_ELEMS (BATCH*NCELL*4*2)   // 16777216
#define WEIGHTS_ELEMS (BATCH*NCELL*4)    // 8388608
#define CTILES 1024                      // 32x32 contrast tiles per image
#define NCONTRAST (BATCH*CTILES)         // 8192

// Scratch (static device globals — allocation-free per harness rules)
__device__ float g_contrast[BATCH*HW];
__device__ float g_bmn[NCONTRAST];
__device__ float g_bmx[NCONTRAST];

// ---------------------------------------------------------------------------
// JAX threefry2x32, key = jax.random.key(42) -> (0, 42)
// ---------------------------------------------------------------------------
__device__ __forceinline__ unsigned rotl32(unsigned x, int r) {
    return __funnelshift_l(x, x, r);
}

__device__ __forceinline__ void threefry2x32(unsigned x0, unsigned x1,
                                             unsigned& o0, unsigned& o1) {
    const unsigned ks0 = 0u, ks1 = 42u, ks2 = 0x1BD11BF0u;
    x0 += ks0; x1 += ks1;
#define TFR(r) { x0 += x1; x1 = rotl32(x1, r); x1 ^= x0; }
    TFR(13) TFR(15) TFR(26) TFR(6)
    x0 += ks1; x1 += ks2 + 1u;
    TFR(17) TFR(29) TFR(16) TFR(24)
    x0 += ks2; x1 += ks0 + 2u;
    TFR(13) TFR(15) TFR(26) TFR(6)
    x0 += ks0; x1 += ks1 + 3u;
    TFR(17) TFR(29) TFR(16) TFR(24)
    x0 += ks1; x1 += ks2 + 4u;
    TFR(13) TFR(15) TFR(26) TFR(6)
    x0 += ks2; x1 += ks0 + 5u;
#undef TFR
    o0 = x0; o1 = x1;
}

// v in [1,2): mantissa bits of the uniform (u = v - 1)
__device__ __forceinline__ float tf_vbits(unsigned flat_idx) {
    unsigned o0, o1;
    threefry2x32(0u, flat_idx, o0, o1);
    unsigned bits = o0 ^ o1;
    return __uint_as_float((bits >> 9) | 0x3f800000u);
}

// folded offset constants:
// coord = base + ((v-1) - 0.5)*0.8*CELLSZ = fma(v, C1, base - C15)
#define CELLSZ 0.00390625f              // 2/512 exact (2^-8)
#define TF_C1  (0.8f * CELLSZ)          // exact scaling of 0.8f
#define TF_C15 (1.5f * TF_C1)

// ---------------------------------------------------------------------------
// K1: strict-alternation mixed-block kernel. Even bid -> contrast tile
// (vectorized interior gray fill + strip compute), odd bid -> threefry
// coords block (1 cell/thread, FFMA-folded epilogue).
// ---------------------------------------------------------------------------
__global__ void k_main1(const float* __restrict__ img,
                        float* __restrict__ coords) {
    __shared__ __align__(16) float sg[36][40];
    __shared__ float wmn[8], wmx[8];

    const int bid = blockIdx.x;
    const int lin = threadIdx.x;

    if ((bid & 1) == 0) {
        // ---------------- contrast tile (32x32, smem gray halo) ------------
        const int cid  = bid >> 1;                 // 0..8191
        const int b    = cid >> 10;
        const int tile = cid & (CTILES - 1);
        const int by0 = (tile >> 5) * 32;
        const int bx0 = (tile & 31) * 32;

        const float* ib = img + (size_t)b * 3 * HW;

        // gray fill into sg[r][c], image col = bx0 + c - 4, row = by0 + r - 2
        if (bx0 != 0 && bx0 != W - 32 && by0 != 0 && by0 != H - 32) {
            // interior: aligned float4 loads, 360 items (36 rows x 10 float4)
            for (int e = lin; e < 360; e += 256) {
                int r = e / 10, c4 = e - r * 10;
                const float* p = ib + (by0 + r - 2) * W + (bx0 - 4) + c4 * 4;
                float4 rr = *(const float4*)p;
                float4 gg = *(const float4*)(p + HW);
                float4 bb = *(const float4*)(p + 2 * HW);
                float4 gv;
                gv.x = rr.x * 0.299f + gg.x * 0.587f + bb.x * 0.114f;
                gv.y = rr.y * 0.299f + gg.y * 0.587f + bb.y * 0.114f;
                gv.z = rr.z * 0.299f + gg.z * 0.587f + bb.z * 0.114f;
                gv.w = rr.w * 0.299f + gg.w * 0.587f + bb.w * 0.114f;
                *(float4*)&sg[r][c4 * 4] = gv;
            }
        } else {
            // border: scalar predicated path (zero outside image)
            for (int e = lin; e < 36 * 40; e += 256) {
                int r = e / 40, c = e - r * 40;
                int gy = by0 + r - 2, gx = bx0 + c - 4;
                float v = 0.0f;
                if ((unsigned)gy < H && (unsigned)gx < W) {
                    int p = gy * W + gx;
                    v = __ldg(ib + p) * 0.299f + __ldg(ib + HW + p) * 0.587f
                      + __ldg(ib + 2 * HW + p) * 0.114f;
                }
                sg[r][c] = v;
            }
        }
        __syncthreads();

        // compute: 8 strips (4 cols) x 32 rows; one strip-row per thread
        const int strip = lin & 7;                 // 0..7
        const int ry    = lin >> 3;                // 0..31
        const int y     = by0 + ry;
        const int ly    = ry + 2;
        const int c0    = strip * 4;
        const int lc    = c0 + 4;                  // sg col of first output

        float r0[6], rc[6], r1[6];
#pragma unroll
        for (int i = 0; i < 6; ++i) {
            r0[i] = sg[ly - 1][lc - 1 + i];
            rc[i] = sg[ly    ][lc - 1 + i];
            r1[i] = sg[ly + 1][lc - 1 + i];
        }

        float cmin = 3.402823466e+38f, cmax = 0.0f;
        float cc[4];
#pragma unroll
        for (int i = 0; i < 4; ++i) {
            float a00 = r0[i], a01 = r0[i+1], a02 = r0[i+2];
            float a10 = rc[i], a11 = rc[i+1], a12 = rc[i+2];
            float a20 = r1[i], a21 = r1[i+1], a22 = r1[i+2];

            float gx2 = (a02 - a00) + 2.0f * (a12 - a10) + (a22 - a20);
            float gy2 = (a20 - a00) + 2.0f * (a21 - a01) + (a22 - a02);
            float sobel = sqrtf(gx2 * gx2 + gy2 * gy2 + 1e-8f);
            float lapl  = fabsf(4.0f * a11 - a01 - a10 - a12 - a21);

            const int x = bx0 + c0 + i;
            float dx = a12 - a10;
            if (x == 0)     dx = rc[3] - rc[1];
            if (x == W - 1) dx = rc[4] - rc[2];
            float dy = a21 - a01;
            if (y == 0)     dy = sg[ly + 2][lc + i] - sg[ly][lc + i];
            if (y == H - 1) dy = sg[ly][lc + i] - sg[ly - 2][lc + i];
            float gradm = sqrtf(dx * dx + dy * dy + 1e-8f);

            cc[i] = 0.5f * sobel + 0.3f * lapl + 0.2f * gradm;
            cmin = fminf(cmin, cc[i]);
            cmax = fmaxf(cmax, cc[i]);
        }
        float4 cv; cv.x = cc[0]; cv.y = cc[1]; cv.z = cc[2]; cv.w = cc[3];
        *(float4*)(g_contrast + b * HW + y * W + bx0 + c0) = cv;

#pragma unroll
        for (int s = 16; s > 0; s >>= 1) {
            cmin = fminf(cmin, __shfl_xor_sync(0xFFFFFFFFu, cmin, s));
            cmax = fmaxf(cmax, __shfl_xor_sync(0xFFFFFFFFu, cmax, s));
        }
        const int wid = lin >> 5;
        if ((lin & 31) == 0) { wmn[wid] = cmin; wmx[wid] = cmax; }
        __syncthreads();
        if (lin == 0) {
            float mn = wmn[0], mx = wmx[0];
#pragma unroll
            for (int s = 1; s < 8; ++s) {
                mn = fminf(mn, wmn[s]);
                mx = fmaxf(mx, wmx[s]);
            }
            g_bmn[cid] = mn;
            g_bmx[cid] = mx;
        }
    } else {
        // ---------------- threefry coords (img-independent, 1 cell/thread) -
        const int t = (bid >> 1) * 256 + lin;   // 0 .. 2M-1
        const int cell = t & (NCELL - 1);
        const int i = cell >> 9;
        const int j = cell & (TW - 1);

        // folded bases: coord = fma(v, TF_C1, base - TF_C15)
        float by2 = (-1.0f + (float)i * (2.0f / 511.0f)) - TF_C15;
        float bx2 = (-1.0f + (float)j * (2.0f / 511.0f)) - TF_C15;

        unsigned ctr = (unsigned)t * 8u;
        float v[8];
#pragma unroll
        for (int s = 0; s < 8; ++s) v[s] = tf_vbits(ctr + s);

        float4 c0, c1;
        c0.x = fmaf(v[0], TF_C1, by2);
        c0.y = fmaf(v[1], TF_C1, bx2);
        c0.z = fmaf(v[2], TF_C1, by2);
        c0.w = fmaf(v[3], TF_C1, bx2);
        c1.x = fmaf(v[4], TF_C1, by2);
        c1.y = fmaf(v[5], TF_C1, bx2);
        c1.z = fmaf(v[6], TF_C1, by2);
        c1.w = fmaf(v[7], TF_C1, bx2);

        float4* cp = (float4*)coords;
        cp[(size_t)t * 2]     = c0;
        cp[(size_t)t * 2 + 1] = c1;
    }
}

// ---------------------------------------------------------------------------
// horizontal 5-tap of zero-padded contrast at row y, cols x4..x4+3.
// ---------------------------------------------------------------------------
__device__ __forceinline__ float4 hconv(const float* __restrict__ cb,
                                        int y, int x4,
                                        float w0, float w1, float w2,
                                        float w3, float w4) {
    float4 r;
    if ((unsigned)y >= H) { r.x = r.y = r.z = r.w = 0.0f; return r; }
    const float* rp = cb + y * W + x4;
    float f0,f1,f2,f3,f4,f5,f6,f7;
    if (x4 >= 4) {
        float4 a = *(const float4*)(rp - 4);
        f0 = a.z; f1 = a.w;
    } else { f0 = f1 = 0.0f; }
    {
        float4 a = *(const float4*)rp;
        f2 = a.x; f3 = a.y; f4 = a.z; f5 = a.w;
    }
    if (x4 + 4 < W) {
        float4 a = *(const float4*)(rp + 4);
        f6 = a.x; f7 = a.y;
    } else { f6 = f7 = 0.0f; }
    r.x = w0*f0 + w1*f1 + w2*f2 + w3*f3 + w4*f4;
    r.y = w0*f1 + w1*f2 + w2*f3 + w3*f4 + w4*f5;
    r.z = w0*f2 + w1*f3 + w2*f4 + w3*f5 + w4*f6;
    r.w = w0*f3 + w1*f4 + w2*f5 + w3*f6 + w4*f7;
    return r;
}

// per-cell weights + ns==1 coords fixup (K1 wrote base+offset coords;
// launch boundary orders the writes).
__device__ __forceinline__ void do_cell(float d, int b, int i, int j,
                                        float* __restrict__ coords,
                                        float* __restrict__ weights) {
    int ns = (d > 0.7f) ? 4 : ((d > 0.4f) ? 2 : 1);
    float wv = d / (float)ns;
    int t = b * NCELL + i * TW + j;
    float4 w4;
    w4.x = wv;
    w4.y = (ns > 1) ? wv : 0.0f;
    w4.z = (ns > 3) ? wv : 0.0f;
    w4.w = (ns > 3) ? wv : 0.0f;
    ((float4*)weights)[t] = w4;
    if (ns == 1) {
        float by = -1.0f + (float)i * (2.0f / 511.0f);
        float bx = -1.0f + (float)j * (2.0f / 511.0f);
        float4 c0; c0.x = by; c0.y = bx; c0.z = by; c0.w = bx;
        float4* cp = (float4*)coords;
        cp[(size_t)t * 2]     = c0;
        cp[(size_t)t * 2 + 1] = c0;
    }
}

// ---------------------------------------------------------------------------
// K2: register-rolling separable gaussian + density + weights + fixup.
// Block (32,8) -> 128x64 tile (1024 blocks); thread owns 4 cols x 8 rows.
// ---------------------------------------------------------------------------
__global__ void __launch_bounds__(256, 4)
k_main2(float* __restrict__ dens_out,
        float* __restrict__ coords,
        float* __restrict__ weights) {
    __shared__ float rmn[8], rmx[8];

    const int b   = blockIdx.z;
    const int bx0 = blockIdx.x * 128;
    const int by0 = blockIdx.y * 64;
    const int tx = threadIdx.x, ty = threadIdx.y;
    const int lin = ty * 32 + tx;

    // --- batch min/max from per-block results (exact: min/max associative)
    {
        float mn_ = 3.402823466e+38f, mx_ = 0.0f;
        for (int e = lin; e < CTILES; e += 256) {
            mn_ = fminf(mn_, g_bmn[b * CTILES + e]);
            mx_ = fmaxf(mx_, g_bmx[b * CTILES + e]);
        }
#pragma unroll
        for (int s = 16; s > 0; s >>= 1) {
            mn_ = fminf(mn_, __shfl_xor_sync(0xFFFFFFFFu, mn_, s));
            mx_ = fmaxf(mx_, __shfl_xor_sync(0xFFFFFFFFu, mx_, s));
        }
        if (tx == 0) { rmn[ty] = mn_; rmx[ty] = mx_; }
    }
    __syncthreads();
    float mn = rmn[0], mx = rmx[0];
#pragma unroll
    for (int s = 1; s < 8; ++s) {
        mn = fminf(mn, rmn[s]);
        mx = fmaxf(mx, rmx[s]);
    }
    const bool ok = mx > mn;
    const float inv = ok ? 1.0f / (mx - mn) : 0.0f;

    // gaussian weights (same fp path as reference)
    const float sg2 = (5.0f / 6.0f) * (5.0f / 6.0f);
    const float e1 = expf(-0.5f / sg2);
    const float e2 = expf(-2.0f / sg2);
    const float ksum = 1.0f + 2.0f * e1 + 2.0f * e2;
    float w[5];
    w[0] = e2 / ksum; w[1] = e1 / ksum; w[2] = 1.0f / ksum; w[3] = w[1]; w[4] = w[0];
    const float w0 = w[0], w1 = w[1], w2 = w[2], w3 = w[3], w4 = w[4];
    const float wsum = ((((w[0] + w[1]) + w[2]) + w[3]) + w[4]);

    const int x4 = bx0 + tx * 4;

    float wxv0 = 0.f, wxv1 = 0.f, wxv2 = 0.f, wxv3 = 0.f;
#pragma unroll
    for (int d = 0; d < 5; ++d) {
        if ((unsigned)(x4 + 0 + d - 2) < W) wxv0 += w[d];
        if ((unsigned)(x4 + 1 + d - 2) < W) wxv1 += w[d];
        if ((unsigned)(x4 + 2 + d - 2) < W) wxv2 += w[d];
        if ((unsigned)(x4 + 3 + d - 2) < W) wxv3 += w[d];
    }

    const float* cb = g_contrast + b * HW;
    const int ys = by0 + ty * 8;

    float4 h0 = hconv(cb, ys - 2, x4, w0, w1, w2, w3, w4);
    float4 h1 = hconv(cb, ys - 1, x4, w0, w1, w2, w3, w4);
    float4 h2 = hconv(cb, ys,     x4, w0, w1, w2, w3, w4);
    float4 h3 = hconv(cb, ys + 1, x4, w0, w1, w2, w3, w4);

    float* drow = dens_out + b * HW + ys * W + x4;

#pragma unroll
    for (int s = 0; s < 8; ++s) {
        const int y = ys + s;
        float4 h4 = hconv(cb, y + 2, x4, w0, w1, w2, w3, w4);

        float4 acc;
        acc.x = w0*h0.x + w1*h1.x + w2*h2.x + w3*h3.x + w4*h4.x;
        acc.y = w0*h0.y + w1*h1.y + w2*h2.y + w3*h3.y + w4*h4.y;
        acc.z = w0*h0.z + w1*h1.z + w2*h2.z + w3*h3.z + w4*h4.z;
        acc.w = w0*h0.w + w1*h1.w + w2*h2.w + w3*h3.w + w4*h4.w;

        float wyv = wsum;
        if (y < 2 || y >= H - 2) {
            wyv = 0.0f;
#pragma unroll
            for (int d = 0; d < 5; ++d)
                if ((unsigned)(y + d - 2) < H) wyv += w[d];
        }

        float4 dv;
        dv.x = 0.1f + 0.9f * sqrtf(fmaxf(inv * (acc.x - mn * (wyv * wxv0)), 0.0f));
        dv.y = 0.1f + 0.9f * sqrtf(fmaxf(inv * (acc.y - mn * (wyv * wxv1)), 0.0f));
        dv.z = 0.1f + 0.9f * sqrtf(fmaxf(inv * (acc.z - mn * (wyv * wxv2)), 0.0f));
        dv.w = 0.1f + 0.9f * sqrtf(fmaxf(inv * (acc.w - mn * (wyv * wxv3)), 0.0f));

        *(float4*)drow = dv;
        drow += W;

        if ((y & 1) == 0) {
            const int i = y >> 1;
            const int j0 = x4 >> 1;
            do_cell(dv.x, b, i, j0,     coords, weights);
            do_cell(dv.z, b, i, j0 + 1, coords, weights);
        }

        h0 = h1; h1 = h2; h2 = h3; h3 = h4;
    }
}

// ---------------------------------------------------------------------------
extern "C" void kernel_launch(void* const* d_in, const int* in_sizes, int n_in,
                              void* d_out, int out_size) {
    const float* img = (const float*)d_in[0];
    float* out = (float*)d_out;
    float* coords  = out;
    float* weights = out + COORDS_ELEMS;
    float* dens    = out + COORDS_ELEMS + WEIGHTS_ELEMS;

    k_main1<<<2 * NCONTRAST, 256>>>(img, coords);
    {
        dim3 grid(W / 128, H / 64, BATCH), block(32, 8);
        k_main2<<<grid, block>>>(dens, coords, weights);
    }
}

// round 15
// speedup vs baseline: 1.0818x; 1.0168x over previous
#include <cuda_runtime.h>
#include <cstdint>

// Problem constants (fixed by setup_inputs)
#define BATCH 8
#define H 1024
#define W 1024
#define HW (H*W)
#define TH 512
#define TW 512
#define NCELL (TH*TW)                    // 262144 = 2^18
#define COORDS_ELEMS (BATCH*NCELL*4*2)   // 16777216
#define WEIGHTS_ELEMS (BATCH*NCELL*4)    // 8388608
#define CTILES 1024                      // 32x32 contrast tiles per image
#define NCONTRAST (BATCH*CTILES)         // 8192
#define NSM 148                          // SM count (B200 sm_100a)
#define NGROUPS 112                      // 56 contrast-groups + 56 tf-groups
#define K1_BLOCKS (NGROUPS * NSM)        // 16576

// Scratch (static device globals — allocation-free per harness rules)
__device__ float g_contrast[BATCH*HW];
__device__ float g_bmn[NCONTRAST];
__device__ float g_bmx[NCONTRAST];

// ---------------------------------------------------------------------------
// JAX threefry2x32, key = jax.random.key(42) -> (0, 42)
// ---------------------------------------------------------------------------
__device__ __forceinline__ unsigned rotl32(unsigned x, int r) {
    return __funnelshift_l(x, x, r);
}

__device__ __forceinline__ void threefry2x32(unsigned x0, unsigned x1,
                                             unsigned& o0, unsigned& o1) {
    const unsigned ks0 = 0u, ks1 = 42u, ks2 = 0x1BD11BF0u;
    x0 += ks0; x1 += ks1;
#define TFR(r) { x0 += x1; x1 = rotl32(x1, r); x1 ^= x0; }
    TFR(13) TFR(15) TFR(26) TFR(6)
    x0 += ks1; x1 += ks2 + 1u;
    TFR(17) TFR(29) TFR(16) TFR(24)
    x0 += ks2; x1 += ks0 + 2u;
    TFR(13) TFR(15) TFR(26) TFR(6)
    x0 += ks0; x1 += ks1 + 3u;
    TFR(17) TFR(29) TFR(16) TFR(24)
    x0 += ks1; x1 += ks2 + 4u;
    TFR(13) TFR(15) TFR(26) TFR(6)
    x0 += ks2; x1 += ks0 + 5u;
#undef TFR
    o0 = x0; o1 = x1;
}

// v in [1,2): mantissa bits of the uniform (u = v - 1)
__device__ __forceinline__ float tf_vbits(unsigned flat_idx) {
    unsigned o0, o1;
    threefry2x32(0u, flat_idx, o0, o1);
    unsigned bits = o0 ^ o1;
    return __uint_as_float((bits >> 9) | 0x3f800000u);
}

// folded offset constants:
// coord = base + ((v-1) - 0.5)*0.8*CELLSZ = fma(v, C1, base - C15)
#define CELLSZ 0.00390625f              // 2/512 exact (2^-8)
#define TF_C1  (0.8f * CELLSZ)          // exact scaling of 0.8f
#define TF_C15 (1.5f * TF_C1)

// ---------------------------------------------------------------------------
// K1: mixed-block fat kernel with 148-RUN interleave. Wave-1 CTA placement
// maps bids {r, r+148, r+296, ...} to one SM (LUT_classic[bid%148]); with
// type = (bid/148)&1 each SM's resident slots ALTERNATE contrast/threefry,
// guaranteeing the alu-saturated tf stream overlaps contrast's memory
// stalls on every SM (bid-parity interleave put same-type blocks per SM).
// ---------------------------------------------------------------------------
__global__ void k_main1(const float* __restrict__ img,
                        float* __restrict__ coords) {
    __shared__ __align__(16) float sg[36][40];
    __shared__ float wmn[8], wmx[8];

    const int bid = blockIdx.x;
    const int lin = threadIdx.x;
    const int grp = bid / NSM;
    const int r_  = bid - grp * NSM;
    const int idx = (grp >> 1) * NSM + r_;      // id within type

    if ((grp & 1) == 0) {
        // ---------------- contrast tile (32x32, smem gray halo) ------------
        if (idx >= NCONTRAST) return;
        const int cid  = idx;
        const int b    = cid >> 10;
        const int tile = cid & (CTILES - 1);
        const int by0 = (tile >> 5) * 32;
        const int bx0 = (tile & 31) * 32;

        const float* ib = img + (size_t)b * 3 * HW;

        // gray fill into sg[r][c], image col = bx0 + c - 4, row = by0 + r - 2
        if (bx0 != 0 && bx0 != W - 32 && by0 != 0 && by0 != H - 32) {
            // interior: aligned float4 loads, 360 items (36 rows x 10 float4)
            for (int e = lin; e < 360; e += 256) {
                int rr_ = e / 10, c4 = e - rr_ * 10;
                const float* p = ib + (by0 + rr_ - 2) * W + (bx0 - 4) + c4 * 4;
                float4 rr = *(const float4*)p;
                float4 gg = *(const float4*)(p + HW);
                float4 bb = *(const float4*)(p + 2 * HW);
                float4 gv;
                gv.x = rr.x * 0.299f + gg.x * 0.587f + bb.x * 0.114f;
                gv.y = rr.y * 0.299f + gg.y * 0.587f + bb.y * 0.114f;
                gv.z = rr.z * 0.299f + gg.z * 0.587f + bb.z * 0.114f;
                gv.w = rr.w * 0.299f + gg.w * 0.587f + bb.w * 0.114f;
                *(float4*)&sg[rr_][c4 * 4] = gv;
            }
        } else {
            // border: scalar predicated path (zero outside image)
            for (int e = lin; e < 36 * 40; e += 256) {
                int rr_ = e / 40, c = e - rr_ * 40;
                int gy = by0 + rr_ - 2, gx = bx0 + c - 4;
                float v = 0.0f;
                if ((unsigned)gy < H && (unsigned)gx < W) {
                    int p = gy * W + gx;
                    v = __ldg(ib + p) * 0.299f + __ldg(ib + HW + p) * 0.587f
                      + __ldg(ib + 2 * HW + p) * 0.114f;
                }
                sg[rr_][c] = v;
            }
        }
        __syncthreads();

        // compute: 8 strips (4 cols) x 32 rows; one strip-row per thread
        const int strip = lin & 7;                 // 0..7
        const int ry    = lin >> 3;                // 0..31
        const int y     = by0 + ry;
        const int ly    = ry + 2;
        const int c0    = strip * 4;
        const int lc    = c0 + 4;                  // sg col of first output

        float r0[6], rc[6], r1[6];
#pragma unroll
        for (int i = 0; i < 6; ++i) {
            r0[i] = sg[ly - 1][lc - 1 + i];
            rc[i] = sg[ly    ][lc - 1 + i];
            r1[i] = sg[ly + 1][lc - 1 + i];
        }

        float cmin = 3.402823466e+38f, cmax = 0.0f;
        float cc[4];
#pragma unroll
        for (int i = 0; i < 4; ++i) {
            float a00 = r0[i], a01 = r0[i+1], a02 = r0[i+2];
            float a10 = rc[i], a11 = rc[i+1], a12 = rc[i+2];
            float a20 = r1[i], a21 = r1[i+1], a22 = r1[i+2];

            float gx2 = (a02 - a00) + 2.0f * (a12 - a10) + (a22 - a20);
            float gy2 = (a20 - a00) + 2.0f * (a21 - a01) + (a22 - a02);
            float sobel = sqrtf(gx2 * gx2 + gy2 * gy2 + 1e-8f);
            float lapl  = fabsf(4.0f * a11 - a01 - a10 - a12 - a21);

            const int x = bx0 + c0 + i;
            float dx = a12 - a10;
            if (x == 0)     dx = rc[3] - rc[1];
            if (x == W - 1) dx = rc[4] - rc[2];
            float dy = a21 - a01;
            if (y == 0)     dy = sg[ly + 2][lc + i] - sg[ly][lc + i];
            if (y == H - 1) dy = sg[ly][lc + i] - sg[ly - 2][lc + i];
            float gradm = sqrtf(dx * dx + dy * dy + 1e-8f);

            cc[i] = 0.5f * sobel + 0.3f * lapl + 0.2f * gradm;
            cmin = fminf(cmin, cc[i]);
            cmax = fmaxf(cmax, cc[i]);
        }
        float4 cv; cv.x = cc[0]; cv.y = cc[1]; cv.z = cc[2]; cv.w = cc[3];
        *(float4*)(g_contrast + b * HW + y * W + bx0 + c0) = cv;

#pragma unroll
        for (int s = 16; s > 0; s >>= 1) {
            cmin = fminf(cmin, __shfl_xor_sync(0xFFFFFFFFu, cmin, s));
            cmax = fmaxf(cmax, __shfl_xor_sync(0xFFFFFFFFu, cmax, s));
        }
        const int wid = lin >> 5;
        if ((lin & 31) == 0) { wmn[wid] = cmin; wmx[wid] = cmax; }
        __syncthreads();
        if (lin == 0) {
            float mn = wmn[0], mx = wmx[0];
#pragma unroll
            for (int s = 1; s < 8; ++s) {
                mn = fminf(mn, wmn[s]);
                mx = fmaxf(mx, wmx[s]);
            }
            g_bmn[cid] = mn;
            g_bmx[cid] = mx;
        }
    } else {
        // ---------------- threefry coords (img-independent, 1 cell/thread) -
        if (idx >= NCONTRAST) return;              // 8192 tf blocks
        const int t = idx * 256 + lin;             // 0 .. 2M-1
        const int cell = t & (NCELL - 1);
        const int i = cell >> 9;
        const int j = cell & (TW - 1);

        // folded bases: coord = fma(v, TF_C1, base - TF_C15)
        float by2 = (-1.0f + (float)i * (2.0f / 511.0f)) - TF_C15;
        float bx2 = (-1.0f + (float)j * (2.0f / 511.0f)) - TF_C15;

        unsigned ctr = (unsigned)t * 8u;
        float v[8];
#pragma unroll
        for (int s = 0; s < 8; ++s) v[s] = tf_vbits(ctr + s);

        float4 c0, c1;
        c0.x = fmaf(v[0], TF_C1, by2);
        c0.y = fmaf(v[1], TF_C1, bx2);
        c0.z = fmaf(v[2], TF_C1, by2);
        c0.w = fmaf(v[3], TF_C1, bx2);
        c1.x = fmaf(v[4], TF_C1, by2);
        c1.y = fmaf(v[5], TF_C1, bx2);
        c1.z = fmaf(v[6], TF_C1, by2);
        c1.w = fmaf(v[7], TF_C1, bx2);

        float4* cp = (float4*)coords;
        cp[(size_t)t * 2]     = c0;
        cp[(size_t)t * 2 + 1] = c1;
    }
}

// ---------------------------------------------------------------------------
// horizontal 5-tap of zero-padded contrast at row y, cols x4..x4+3.
// ---------------------------------------------------------------------------
__device__ __forceinline__ float4 hconv(const float* __restrict__ cb,
                                        int y, int x4,
                                        float w0, float w1, float w2,
                                        float w3, float w4) {
    float4 r;
    if ((unsigned)y >= H) { r.x = r.y = r.z = r.w = 0.0f; return r; }
    const float* rp = cb + y * W + x4;
    float f0,f1,f2,f3,f4,f5,f6,f7;
    if (x4 >= 4) {
        float4 a = *(const float4*)(rp - 4);
        f0 = a.z; f1 = a.w;
    } else { f0 = f1 = 0.0f; }
    {
        float4 a = *(const float4*)rp;
        f2 = a.x; f3 = a.y; f4 = a.z; f5 = a.w;
    }
    if (x4 + 4 < W) {
        float4 a = *(const float4*)(rp + 4);
        f6 = a.x; f7 = a.y;
    } else { f6 = f7 = 0.0f; }
    r.x = w0*f0 + w1*f1 + w2*f2 + w3*f3 + w4*f4;
    r.y = w0*f1 + w1*f2 + w2*f3 + w3*f4 + w4*f5;
    r.z = w0*f2 + w1*f3 + w2*f4 + w3*f5 + w4*f6;
    r.w = w0*f3 + w1*f4 + w2*f5 + w3*f6 + w4*f7;
    return r;
}

// per-cell weights + ns==1 coords fixup (K1 wrote base+offset coords;
// launch boundary orders the writes).
__device__ __forceinline__ void do_cell(float d, int b, int i, int j,
                                        float* __restrict__ coords,
                                        float* __restrict__ weights) {
    int ns = (d > 0.7f) ? 4 : ((d > 0.4f) ? 2 : 1);
    float wv = d / (float)ns;
    int t = b * NCELL + i * TW + j;
    float4 w4;
    w4.x = wv;
    w4.y = (ns > 1) ? wv : 0.0f;
    w4.z = (ns > 3) ? wv : 0.0f;
    w4.w = (ns > 3) ? wv : 0.0f;
    ((float4*)weights)[t] = w4;
    if (ns == 1) {
        float by = -1.0f + (float)i * (2.0f / 511.0f);
        float bx = -1.0f + (float)j * (2.0f / 511.0f);
        float4 c0; c0.x = by; c0.y = bx; c0.z = by; c0.w = bx;
        float4* cp = (float4*)coords;
        cp[(size_t)t * 2]     = c0;
        cp[(size_t)t * 2 + 1] = c0;
    }
}

// ---------------------------------------------------------------------------
// K2: register-rolling separable gaussian + density + weights + fixup.
// Block (32,8) -> 128x64 tile (1024 blocks); thread owns 4 cols x 8 rows.
// ---------------------------------------------------------------------------
__global__ void __launch_bounds__(256, 4)
k_main2(float* __restrict__ dens_out,
        float* __restrict__ coords,
        float* __restrict__ weights) {
    __shared__ float rmn[8], rmx[8];

    const int b   = blockIdx.z;
    const int bx0 = blockIdx.x * 128;
    const int by0 = blockIdx.y * 64;
    const int tx = threadIdx.x, ty = threadIdx.y;
    const int lin = ty * 32 + tx;

    // --- batch min/max from per-block results (exact: min/max associative)
    {
        float mn_ = 3.402823466e+38f, mx_ = 0.0f;
        for (int e = lin; e < CTILES; e += 256) {
            mn_ = fminf(mn_, g_bmn[b * CTILES + e]);
            mx_ = fmaxf(mx_, g_bmx[b * CTILES + e]);
        }
#pragma unroll
        for (int s = 16; s > 0; s >>= 1) {
            mn_ = fminf(mn_, __shfl_xor_sync(0xFFFFFFFFu, mn_, s));
            mx_ = fmaxf(mx_, __shfl_xor_sync(0xFFFFFFFFu, mx_, s));
        }
        if (tx == 0) { rmn[ty] = mn_; rmx[ty] = mx_; }
    }
    __syncthreads();
    float mn = rmn[0], mx = rmx[0];
#pragma unroll
    for (int s = 1; s < 8; ++s) {
        mn = fminf(mn, rmn[s]);
        mx = fmaxf(mx, rmx[s]);
    }
    const bool ok = mx > mn;
    const float inv = ok ? 1.0f / (mx - mn) : 0.0f;

    // gaussian weights (same fp path as reference)
    const float sg2 = (5.0f / 6.0f) * (5.0f / 6.0f);
    const float e1 = expf(-0.5f / sg2);
    const float e2 = expf(-2.0f / sg2);
    const float ksum = 1.0f + 2.0f * e1 + 2.0f * e2;
    float w[5];
    w[0] = e2 / ksum; w[1] = e1 / ksum; w[2] = 1.0f / ksum; w[3] = w[1]; w[4] = w[0];
    const float w0 = w[0], w1 = w[1], w2 = w[2], w3 = w[3], w4 = w[4];
    const float wsum = ((((w[0] + w[1]) + w[2]) + w[3]) + w[4]);

    const int x4 = bx0 + tx * 4;

    float wxv0 = 0.f, wxv1 = 0.f, wxv2 = 0.f, wxv3 = 0.f;
#pragma unroll
    for (int d = 0; d < 5; ++d) {
        if ((unsigned)(x4 + 0 + d - 2) < W) wxv0 += w[d];
        if ((unsigned)(x4 + 1 + d - 2) < W) wxv1 += w[d];
        if ((unsigned)(x4 + 2 + d - 2) < W) wxv2 += w[d];
        if ((unsigned)(x4 + 3 + d - 2) < W) wxv3 += w[d];
    }

    const float* cb = g_contrast + b * HW;
    const int ys = by0 + ty * 8;

    float4 h0 = hconv(cb, ys - 2, x4, w0, w1, w2, w3, w4);
    float4 h1 = hconv(cb, ys - 1, x4, w0, w1, w2, w3, w4);
    float4 h2 = hconv(cb, ys,     x4, w0, w1, w2, w3, w4);
    float4 h3 = hconv(cb, ys + 1, x4, w0, w1, w2, w3, w4);

    float* drow = dens_out + b * HW + ys * W + x4;

#pragma unroll
    for (int s = 0; s < 8; ++s) {
        const int y = ys + s;
        float4 h4 = hconv(cb, y + 2, x4, w0, w1, w2, w3, w4);

        float4 acc;
        acc.x = w0*h0.x + w1*h1.x + w2*h2.x + w3*h3.x + w4*h4.x;
        acc.y = w0*h0.y + w1*h1.y + w2*h2.y + w3*h3.y + w4*h4.y;
        acc.z = w0*h0.z + w1*h1.z + w2*h2.z + w3*h3.z + w4*h4.z;
        acc.w = w0*h0.w + w1*h1.w + w2*h2.w + w3*h3.w + w4*h4.w;

        float wyv = wsum;
        if (y < 2 || y >= H - 2) {
            wyv = 0.0f;
#pragma unroll
            for (int d = 0; d < 5; ++d)
                if ((unsigned)(y + d - 2) < H) wyv += w[d];
        }

        float4 dv;
        dv.x = 0.1f + 0.9f * sqrtf(fmaxf(inv * (acc.x - mn * (wyv * wxv0)), 0.0f));
        dv.y = 0.1f + 0.9f * sqrtf(fmaxf(inv * (acc.y - mn * (wyv * wxv1)), 0.0f));
        dv.z = 0.1f + 0.9f * sqrtf(fmaxf(inv * (acc.z - mn * (wyv * wxv2)), 0.0f));
        dv.w = 0.1f + 0.9f * sqrtf(fmaxf(inv * (acc.w - mn * (wyv * wxv3)), 0.0f));

        *(float4*)drow = dv;
        drow += W;

        if ((y & 1) == 0) {
            const int i = y >> 1;
            const int j0 = x4 >> 1;
            do_cell(dv.x, b, i, j0,     coords, weights);
            do_cell(dv.z, b, i, j0 + 1, coords, weights);
        }

        h0 = h1; h1 = h2; h2 = h3; h3 = h4;
    }
}

// ---------------------------------------------------------------------------
extern "C" void kernel_launch(void* const* d_in, const int* in_sizes, int n_in,
                              void* d_out, int out_size) {
    const float* img = (const float*)d_in[0];
    float* out = (float*)d_out;
    float* coords  = out;
    float* weights = out + COORDS_ELEMS;
    float* dens    = out + COORDS_ELEMS + WEIGHTS_ELEMS;

    k_main1<<<K1_BLOCKS, 256>>>(img, coords);
    {
        dim3 grid(W / 128, H / 64, BATCH), block(32, 8);
        k_main2<<<grid, block>>>(dens, coords, weights);
    }
}